// round 3
// baseline (speedup 1.0000x reference)
#include <cuda_runtime.h>
#include <math.h>

// ---- packed f32x2 helpers (sm_103a FFMA2 — only reachable via PTX) --------
typedef unsigned long long u64;
__device__ __forceinline__ u64 pk2(float lo, float hi) {
    u64 r; asm("mov.b64 %0, {%1, %2};" : "=l"(r) : "f"(lo), "f"(hi)); return r;
}
__device__ __forceinline__ float2 up2(u64 v) {
    float2 r; asm("mov.b64 {%0, %1}, %2;" : "=f"(r.x), "=f"(r.y) : "l"(v)); return r;
}
__device__ __forceinline__ void fma2(u64& d, u64 a, u64 b) {
    asm("fma.rn.f32x2 %0, %1, %2, %0;" : "+l"(d) : "l"(a), "l"(b));
}
__device__ __forceinline__ u64 lds2(const float2* p) {
    return *(const u64*)p;
}

// Intermediate activations (static device globals — no runtime allocation).
__device__ float g_a1[32*50*32*64];    // after L1 (conv+pool+relu)   [32,50,32,64]
__device__ float g_a2[32*50*16*16];    // after L2 (conv+pool+relu)   [32,50,16,16]
__device__ float g_a2c[16*50*16*16];   // after combine               [16,50,16,16]
__device__ float g_a3[16*50*32*64];    // after L3 (up+conv+relu)     [16,50,32,64]
__device__ float g_a4[16*50*64*256];   // after L4 (up+conv+relu)     [16,50,64,256]

// ---------------------------------------------------------------------------
// K1: conv1 (1->50, 3x7 circular on 64x256) + maxpool(2,4) + relu.
// Batch-paired f32x2: grid (8 strips, 16 bpairs), 256 threads.
// ---------------------------------------------------------------------------
__global__ void k1(const float* __restrict__ x, const float* __restrict__ w1,
                   const float* __restrict__ b1) {
    __shared__ float2 sx[10][256];
    __shared__ float2 sw[1050];
    const int bp = blockIdx.y, strip = blockIdx.x;
    const int b0 = 2*bp, b1i = 2*bp + 1;
    const int tid = threadIdx.x;
    const float* xb0 = x + b0*64*256;
    const float* xb1 = x + b1i*64*256;
    for (int idx = tid; idx < 2560; idx += 256) {
        int l = idx >> 8, col = idx & 255;
        int row = (strip*8 - 2 + l) & 63;
        sx[l][col] = make_float2(xb0[row*256 + col], xb1[row*256 + col]);
    }
    for (int idx = tid; idx < 1050; idx += 256) {
        float w = w1[idx]; sw[idx] = make_float2(w, w);
    }
    __syncthreads();

    const int prl = tid >> 6;          // pooled row within strip 0..3
    const int pw  = tid & 63;          // pooled col 0..63
    u64 xv[4][10];
    #pragma unroll
    for (int rl = 0; rl < 4; rl++)
        #pragma unroll
        for (int j = 0; j < 10; j++)
            xv[rl][j] = lds2(&sx[prl*2 + rl][(pw*4 - 6 + j) & 255]);

    const int pr = strip*4 + prl;
    for (int co = 0; co < 50; co++) {
        u64 acc[8];
        #pragma unroll
        for (int i = 0; i < 8; i++) acc[i] = 0ULL;
        #pragma unroll
        for (int p = 0; p < 3; p++)
            #pragma unroll
            for (int q = 0; q < 7; q++) {
                u64 wv = lds2(&sw[co*21 + p*7 + q]);
                #pragma unroll
                for (int dr = 0; dr < 2; dr++)
                    #pragma unroll
                    for (int dc = 0; dc < 4; dc++)
                        fma2(acc[dr*4+dc], xv[dr + 2 - p][dc + 6 - q], wv);
            }
        float2 a0 = up2(acc[0]);
        float mx = a0.x, my = a0.y;
        #pragma unroll
        for (int i = 1; i < 8; i++) {
            float2 a = up2(acc[i]);
            mx = fmaxf(mx, a.x); my = fmaxf(my, a.y);
        }
        float bb = b1[co];
        g_a1[((b0 *50 + co)*32 + pr)*64 + pw] = fmaxf(mx + bb, 0.f);
        g_a1[((b1i*50 + co)*32 + pr)*64 + pw] = fmaxf(my + bb, 0.f);
    }
}

// ---------------------------------------------------------------------------
// K2: conv2 (50->50, 3x7 circular on 32x64) + maxpool(2,4) + relu.
// Batch-paired f32x2. grid (32 = 16 r * 2 cog, 16 bpairs), 400 threads:
// pw = tid&15, co_local = tid>>4 (25 couts per block half).
// Weights pre-duplicated (w,w) in smem -> LDS.64 broadcast.
// ---------------------------------------------------------------------------
__global__ void k2(const float* __restrict__ w2, const float* __restrict__ b2) {
    __shared__ float2 sx[5][4][64];      // [cin-chunk][conv row][col]
    __shared__ float2 sw[25*5*21];       // [co_local][cin-chunk][tap], (w,w)
    const int rx = blockIdx.x, bp = blockIdx.y;
    const int r = rx >> 1, cog = rx & 1;
    const int b0 = 2*bp, b1i = 2*bp + 1;
    const int tid = threadIdx.x;
    const int pw = tid & 15, co_l = tid >> 4;   // co_l in 0..24
    const int co = cog*25 + co_l;

    u64 acc[8];
    #pragma unroll
    for (int i = 0; i < 8; i++) acc[i] = 0ULL;

    for (int cb = 0; cb < 50; cb += 5) {
        __syncthreads();
        for (int idx = tid; idx < 5*4*64; idx += 400) {
            int cl = idx >> 8, l = (idx >> 6) & 3, col = idx & 63;
            int row = (2*r - 2 + l) & 31;
            int off = ((cb + cl)*32 + row)*64 + col;
            sx[cl][l][col] = make_float2(g_a1[(b0*50)*2048 + off],
                                         g_a1[(b1i*50)*2048 + off]);
        }
        for (int idx = tid; idx < 25*105; idx += 400) {
            int wo = idx / 105, rem = idx - wo*105;
            float w = w2[(cog*25 + wo)*1050 + cb*21 + rem];
            sw[idx] = make_float2(w, w);
        }
        __syncthreads();
        #pragma unroll
        for (int cl = 0; cl < 5; cl++) {
            u64 xv[4][10];
            #pragma unroll
            for (int l = 0; l < 4; l++)
                #pragma unroll
                for (int j = 0; j < 10; j++)
                    xv[l][j] = lds2(&sx[cl][l][(pw*4 - 6 + j) & 63]);
            const float2* swc = &sw[(co_l*5 + cl)*21];
            #pragma unroll
            for (int p = 0; p < 3; p++)
                #pragma unroll
                for (int q = 0; q < 7; q++) {
                    u64 wv = lds2(&swc[p*7 + q]);
                    #pragma unroll
                    for (int dc = 0; dc < 4; dc++) {
                        fma2(acc[dc],     xv[2 - p][dc + 6 - q], wv);
                        fma2(acc[4 + dc], xv[3 - p][dc + 6 - q], wv);
                    }
                }
        }
    }
    float2 a0 = up2(acc[0]);
    float mx = a0.x, my = a0.y;
    #pragma unroll
    for (int i = 1; i < 8; i++) {
        float2 a = up2(acc[i]);
        mx = fmaxf(mx, a.x); my = fmaxf(my, a.y);
    }
    float bb = b2[co];
    g_a2[((b0 *50 + co)*16 + r)*16 + pw] = fmaxf(mx + bb, 0.f);
    g_a2[((b1i*50 + co)*16 + r)*16 + pw] = fmaxf(my + bb, 0.f);
}

// ---------------------------------------------------------------------------
// K3: combine: out[b] = a2[2b] + mean_{hw}(a2[2b+1]).  grid 800 = 16*50.
// ---------------------------------------------------------------------------
__global__ void k3() {
    const int bc = blockIdx.x;
    const int b = bc / 50, c = bc % 50;
    const int t = threadIdx.x;
    const float* ev = g_a2 + ((2*b)*50 + c)*256;
    const float* od = g_a2 + ((2*b + 1)*50 + c)*256;
    __shared__ float red[256];
    red[t] = od[t];
    __syncthreads();
    for (int s = 128; s > 0; s >>= 1) {
        if (t < s) red[t] += red[t + s];
        __syncthreads();
    }
    float mean = red[0] * (1.f/256.f);
    g_a2c[(b*50 + c)*256 + t] = ev[t] + mean;
}

// ---------------------------------------------------------------------------
// K4: zero-upsample(2,4) + conv3 (50->50, 3x5 circular on 32x64) + relu.
// Batch-paired f32x2. grid (32 h, 8 bpairs), 256 threads; thread t<200 owns
// (co=t/4, cls=t%4) and all 16 w-positions of its class.
// ---------------------------------------------------------------------------
__global__ void k4(const float* __restrict__ w3, const float* __restrict__ b3) {
    __shared__ float2 sxd[50][2][16];
    const int bp = blockIdx.y, h = blockIdx.x;
    const int b0 = 2*bp, b1i = 2*bp + 1;
    const int tid = threadIdx.x;
    const int hodd = h & 1;
    const int pA = hodd ? 1 : 0;
    const int rowA = ((h - pA) & 31) >> 1;
    const int rowB = ((h - 2) & 31) >> 1;
    for (int idx = tid; idx < 1600; idx += 256) {
        int cin = idx >> 5, slot = (idx >> 4) & 1, col = idx & 15;
        int row = slot ? rowB : rowA;
        int off = (cin*16 + row)*16 + col;
        sxd[cin][slot][col] = make_float2(g_a2c[(b0*50)*256 + off],
                                          g_a2c[(b1i*50)*256 + off]);
    }
    __syncthreads();

    if (tid < 200) {
        const int co = tid >> 2, cls = tid & 3;
        u64 acc[16];
        #pragma unroll
        for (int j = 0; j < 16; j++) acc[j] = 0ULL;

        #pragma unroll 2
        for (int cin = 0; cin < 50; cin++) {
            const float* wp = w3 + (co*50 + cin)*15;
            {
                u64 xr[16];
                #pragma unroll
                for (int jj = 0; jj < 8; jj++) {
                    ulonglong2 v = *(const ulonglong2*)&sxd[cin][0][jj*2];
                    xr[jj*2] = v.x; xr[jj*2+1] = v.y;
                }
                float w0s = __ldg(&wp[pA*5 + cls]);
                u64 w0 = pk2(w0s, w0s);
                #pragma unroll
                for (int j = 0; j < 16; j++) fma2(acc[j], xr[j], w0);
                if (cls == 0) {
                    float w1s = __ldg(&wp[pA*5 + 4]);
                    u64 w1 = pk2(w1s, w1s);
                    #pragma unroll
                    for (int j = 0; j < 16; j++)
                        fma2(acc[j], xr[(j + 15) & 15], w1);
                }
            }
            if (!hodd) {
                u64 xr[16];
                #pragma unroll
                for (int jj = 0; jj < 8; jj++) {
                    ulonglong2 v = *(const ulonglong2*)&sxd[cin][1][jj*2];
                    xr[jj*2] = v.x; xr[jj*2+1] = v.y;
                }
                float w0s = __ldg(&wp[10 + cls]);
                u64 w0 = pk2(w0s, w0s);
                #pragma unroll
                for (int j = 0; j < 16; j++) fma2(acc[j], xr[j], w0);
                if (cls == 0) {
                    float w1s = __ldg(&wp[10 + 4]);
                    u64 w1 = pk2(w1s, w1s);
                    #pragma unroll
                    for (int j = 0; j < 16; j++)
                        fma2(acc[j], xr[(j + 15) & 15], w1);
                }
            }
        }
        float bb = b3[co];
        #pragma unroll
        for (int j = 0; j < 16; j++) {
            float2 a = up2(acc[j]);
            int off = (co*32 + h)*64 + cls + 4*j;
            g_a3[(b0 *50)*2048 + off] = fmaxf(a.x + bb, 0.f);
            g_a3[(b1i*50)*2048 + off] = fmaxf(a.y + bb, 0.f);
        }
    }
}

// ---------------------------------------------------------------------------
// K5: zero-upsample(2,4) + conv4 (50->50, 3x7 circular on 64x256) + relu.
// Batch-paired f32x2. grid (128 = h*2 halves, 8 bpairs), 224 threads;
// thread t<200 owns (co=t/4, cls=t%4), 32 w-positions of its class.
// ---------------------------------------------------------------------------
__global__ void k5(const float* __restrict__ w4, const float* __restrict__ b4) {
    __shared__ float2 sxd[50][2][64];
    const int bp = blockIdx.y, hx = blockIdx.x;
    const int h = hx >> 1, h2 = hx & 1;
    const int b0 = 2*bp, b1i = 2*bp + 1;
    const int tid = threadIdx.x;
    const int hodd = h & 1;
    const int pA = hodd ? 1 : 0;
    const int rowA = ((h - pA) & 63) >> 1;
    const int rowB = ((h - 2) & 63) >> 1;
    for (int idx = tid; idx < 6400; idx += 224) {
        int cin = idx >> 7, slot = (idx >> 6) & 1, col = idx & 63;
        int row = slot ? rowB : rowA;
        int off = (cin*32 + row)*64 + col;
        sxd[cin][slot][col] = make_float2(g_a3[(b0*50)*2048 + off],
                                          g_a3[(b1i*50)*2048 + off]);
    }
    __syncthreads();

    if (tid < 200) {
        const int co = tid >> 2, cls = tid & 3;
        const int bcol = h2*32;
        const int colm = (bcol + 63) & 63;   // bcol-1 mod 64
        u64 acc[32];
        #pragma unroll
        for (int j = 0; j < 32; j++) acc[j] = 0ULL;

        for (int cin = 0; cin < 50; cin++) {
            const float* wp = w4 + (co*50 + cin)*21;
            {
                u64 xr[32];
                #pragma unroll
                for (int jj = 0; jj < 16; jj++) {
                    ulonglong2 v = *(const ulonglong2*)&sxd[cin][0][bcol + jj*2];
                    xr[jj*2] = v.x; xr[jj*2+1] = v.y;
                }
                u64 xm = lds2(&sxd[cin][0][colm]);
                float w0s = __ldg(&wp[pA*7 + cls]);
                u64 w0 = pk2(w0s, w0s);
                #pragma unroll
                for (int j = 0; j < 32; j++) fma2(acc[j], xr[j], w0);
                if (cls < 3) {
                    float w1s = __ldg(&wp[pA*7 + cls + 4]);
                    u64 w1 = pk2(w1s, w1s);
                    fma2(acc[0], xm, w1);
                    #pragma unroll
                    for (int j = 1; j < 32; j++) fma2(acc[j], xr[j-1], w1);
                }
            }
            if (!hodd) {
                u64 xr[32];
                #pragma unroll
                for (int jj = 0; jj < 16; jj++) {
                    ulonglong2 v = *(const ulonglong2*)&sxd[cin][1][bcol + jj*2];
                    xr[jj*2] = v.x; xr[jj*2+1] = v.y;
                }
                u64 xm = lds2(&sxd[cin][1][colm]);
                float w0s = __ldg(&wp[14 + cls]);
                u64 w0 = pk2(w0s, w0s);
                #pragma unroll
                for (int j = 0; j < 32; j++) fma2(acc[j], xr[j], w0);
                if (cls < 3) {
                    float w1s = __ldg(&wp[14 + cls + 4]);
                    u64 w1 = pk2(w1s, w1s);
                    fma2(acc[0], xm, w1);
                    #pragma unroll
                    for (int j = 1; j < 32; j++) fma2(acc[j], xr[j-1], w1);
                }
            }
        }
        float bb = b4[co];
        #pragma unroll
        for (int j = 0; j < 32; j++) {
            float2 a = up2(acc[j]);
            int off = (co*64 + h)*256 + cls + 4*(bcol + j);
            g_a4[(b0 *50)*16384 + off] = fmaxf(a.x + bb, 0.f);
            g_a4[(b1i*50)*16384 + off] = fmaxf(a.y + bb, 0.f);
        }
    }
}

// ---------------------------------------------------------------------------
// K6: conv5 (50->1, 3x7 circular on 64x256) + sigmoid. Batch-paired f32x2.
// grid (16 h-quads, 8 bpairs), 256 threads (one col each, 4 output rows).
// cin chunked by 5; each x-load feeds up to 3 taps (row reuse).
// ---------------------------------------------------------------------------
__global__ void k6(const float* __restrict__ w5, const float* __restrict__ b5,
                   float* __restrict__ out) {
    __shared__ float2 sxc[5][6][256];   // [cin-chunk][input row][col]
    __shared__ float2 swk[1050];        // (w,w)
    const int bp = blockIdx.y, hq = blockIdx.x;
    const int h0 = hq*4;
    const int b0 = 2*bp, b1i = 2*bp + 1;
    const int tid = threadIdx.x;
    for (int idx = tid; idx < 1050; idx += 256) {
        float w = w5[idx]; swk[idx] = make_float2(w, w);
    }

    u64 acc[4];
    #pragma unroll
    for (int i = 0; i < 4; i++) acc[i] = 0ULL;

    for (int cb = 0; cb < 50; cb += 5) {
        __syncthreads();
        for (int idx = tid; idx < 5*6*256; idx += 256) {
            int cl = idx / 1536, rr = (idx >> 8) % 6, col = idx & 255;
            int inrow = (h0 - 2 + rr) & 63;
            int off = ((cb + cl)*64 + inrow)*256 + col;
            sxc[cl][rr][col] = make_float2(g_a4[(b0*50)*16384 + off],
                                           g_a4[(b1i*50)*16384 + off]);
        }
        __syncthreads();
        #pragma unroll
        for (int cl = 0; cl < 5; cl++) {
            u64 wv[21];
            #pragma unroll
            for (int t = 0; t < 21; t++)
                wv[t] = lds2(&swk[(cb + cl)*21 + t]);
            #pragma unroll
            for (int rr = 0; rr < 6; rr++) {
                u64 xv[7];
                #pragma unroll
                for (int q = 0; q < 7; q++)
                    xv[q] = lds2(&sxc[cl][rr][(tid - q) & 255]);
                #pragma unroll
                for (int i = 0; i < 4; i++) {
                    int p = i - rr + 2;
                    if (p >= 0 && p <= 2) {
                        #pragma unroll
                        for (int q = 0; q < 7; q++)
                            fma2(acc[i], xv[q], wv[p*7 + q]);
                    }
                }
            }
        }
    }
    float bb = b5[0];
    #pragma unroll
    for (int i = 0; i < 4; i++) {
        float2 a = up2(acc[i]);
        float zx = a.x + bb, zy = a.y + bb;
        out[(b0 *64 + h0 + i)*256 + tid] = 1.f / (1.f + expf(-zx));
        out[(b1i*64 + h0 + i)*256 + tid] = 1.f / (1.f + expf(-zy));
    }
}

// ---------------------------------------------------------------------------
extern "C" void kernel_launch(void* const* d_in, const int* in_sizes, int n_in,
                              void* d_out, int out_size) {
    const float* x  = (const float*)d_in[0];
    const float* w1 = (const float*)d_in[1];
    const float* b1 = (const float*)d_in[2];
    const float* w2 = (const float*)d_in[3];
    const float* b2 = (const float*)d_in[4];
    const float* w3 = (const float*)d_in[5];
    const float* b3 = (const float*)d_in[6];
    const float* w4 = (const float*)d_in[7];
    const float* b4 = (const float*)d_in[8];
    const float* w5 = (const float*)d_in[9];
    const float* b5 = (const float*)d_in[10];
    float* out = (float*)d_out;

    k1<<<dim3(8, 16), 256>>>(x, w1, b1);
    k2<<<dim3(32, 16), 400>>>(w2, b2);
    k3<<<800, 256>>>();
    k4<<<dim3(32, 8), 256>>>(w3, b3);
    k5<<<dim3(128, 8), 224>>>(w4, b4);
    k6<<<dim3(16, 8), 256>>>(w5, b5, out);
}

// round 5
// speedup vs baseline: 1.4359x; 1.4359x over previous
#include <cuda_runtime.h>
#include <math.h>

// ---- packed f32x2 helpers (sm_103a FFMA2 — only reachable via PTX) --------
typedef unsigned long long u64;
__device__ __forceinline__ u64 pk2(float lo, float hi) {
    u64 r; asm("mov.b64 %0, {%1, %2};" : "=l"(r) : "f"(lo), "f"(hi)); return r;
}
__device__ __forceinline__ float2 up2(u64 v) {
    float2 r; asm("mov.b64 {%0, %1}, %2;" : "=f"(r.x), "=f"(r.y) : "l"(v)); return r;
}
__device__ __forceinline__ void fma2(u64& d, u64 a, u64 b) {
    asm("fma.rn.f32x2 %0, %1, %2, %0;" : "+l"(d) : "l"(a), "l"(b));
}
__device__ __forceinline__ u64 lds2(const float2* p) {
    return *(const u64*)p;
}
// skewed smem index: conflict-free for strided warp access patterns
__device__ __forceinline__ int swz(int m) { return m + (m >> 3); }

// Intermediate activations (static device globals — no runtime allocation).
__device__ float g_a1[32*50*32*64];    // after L1 (conv+pool+relu)   [32,50,32,64]
__device__ float g_a2[32*50*16*16];    // after L2 (conv+pool+relu)   [32,50,16,16]
__device__ float g_a2c[16*50*16*16];   // after combine               [16,50,16,16]
__device__ float g_a3[16*50*32*64];    // after L3 (up+conv+relu)     [16,50,32,64]
__device__ float g_a4[16*50*64*256];   // after L4 (up+conv+relu)     [16,50,64,256]

// ---------------------------------------------------------------------------
// K1: circular conv1 (1->50, 3x7 on 64x256) + maxpool(2,4) + relu
// (R2 version — compute-bound, adequate.)
// ---------------------------------------------------------------------------
__global__ void k1(const float* __restrict__ x, const float* __restrict__ w1,
                   const float* __restrict__ b1) {
    __shared__ float sx[10][256];
    __shared__ float sw[50*21];
    const int b = blockIdx.y, strip = blockIdx.x;
    const int tid = threadIdx.x;
    const float* xb = x + b*64*256;
    for (int idx = tid; idx < 10*256; idx += 256) {
        int l = idx >> 8, col = idx & 255;
        int row = (strip*8 - 2 + l) & 63;
        sx[l][col] = xb[row*256 + col];
    }
    for (int idx = tid; idx < 1050; idx += 256) sw[idx] = w1[idx];
    __syncthreads();

    const int prl = tid >> 6;
    const int pw  = tid & 63;
    float xv[4][10];
    #pragma unroll
    for (int rl = 0; rl < 4; rl++)
        #pragma unroll
        for (int j = 0; j < 10; j++)
            xv[rl][j] = sx[prl*2 + rl][(pw*4 - 6 + j) & 255];

    const int pr = strip*4 + prl;
    for (int co = 0; co < 50; co++) {
        float acc[8];
        #pragma unroll
        for (int i = 0; i < 8; i++) acc[i] = 0.f;
        #pragma unroll
        for (int p = 0; p < 3; p++)
            #pragma unroll
            for (int q = 0; q < 7; q++) {
                float wv = sw[co*21 + p*7 + q];
                #pragma unroll
                for (int dr = 0; dr < 2; dr++)
                    #pragma unroll
                    for (int dc = 0; dc < 4; dc++)
                        acc[dr*4+dc] += wv * xv[dr + 2 - p][dc + 6 - q];
            }
        float m = acc[0];
        #pragma unroll
        for (int i = 1; i < 8; i++) m = fmaxf(m, acc[i]);
        g_a1[((b*50 + co)*32 + pr)*64 + pw] = fmaxf(m + b1[co], 0.f);
    }
}

// ---------------------------------------------------------------------------
// K2: conv2 (50->50, 3x7 circular on 32x64) + maxpool(2,4) + relu. f32x2.
// grid (32 = 16 r x 2 cog, 16 bpairs), 200 threads: cp = tid&7 (8 conv-col
// group), co_l = tid>>3 (25 couts). Per thread: 2 conv rows x 8 conv cols,
// weights cached in regs, skewed smem -> compute-bound.
// ---------------------------------------------------------------------------
__global__ void __launch_bounds__(200, 2)
k2(const float* __restrict__ w2, const float* __restrict__ b2) {
    __shared__ float2 sx[5][4][72];     // [cin-chunk][conv row][skewed col]
    const int rx = blockIdx.x, bp = blockIdx.y;
    const int r = rx >> 1, cog = rx & 1;
    const int b0 = 2*bp, b1i = 2*bp + 1;
    const int tid = threadIdx.x;
    const int cp = tid & 7, co_l = tid >> 3;    // co_l 0..24
    const int co = cog*25 + co_l;
    const float* a1b0 = g_a1 + b0*50*2048;
    const float* a1b1 = g_a1 + b1i*50*2048;

    u64 acc0[8], acc1[8];
    #pragma unroll
    for (int i = 0; i < 8; i++) { acc0[i] = 0ULL; acc1[i] = 0ULL; }

    #pragma unroll 1
    for (int cb = 0; cb < 50; cb += 5) {
        __syncthreads();
        for (int idx = tid; idx < 5*4*64; idx += 200) {
            int cl = idx >> 8, l = (idx >> 6) & 3, m = idx & 63;
            int row = (2*r - 2 + l) & 31;
            int off = ((cb + cl)*32 + row)*64 + m;
            sx[cl][l][swz(m)] = make_float2(a1b0[off], a1b1[off]);
        }
        __syncthreads();
        #pragma unroll 1
        for (int cl = 0; cl < 5; cl++) {
            const float* wp = w2 + (co*50 + cb + cl)*21;
            u64 wv[21];
            #pragma unroll
            for (int t = 0; t < 21; t++) {
                float s = __ldg(&wp[t]); wv[t] = pk2(s, s);
            }
            #pragma unroll
            for (int l = 0; l < 4; l++) {
                u64 xv[14];
                #pragma unroll
                for (int j = 0; j < 14; j++) {
                    int m = (cp*8 - 6 + j) & 63;
                    xv[j] = lds2(&sx[cl][l][swz(m)]);
                }
                if (l <= 2) {          // dr=0 row, p = 2-l
                    const int p = 2 - l;
                    #pragma unroll
                    for (int q = 0; q < 7; q++)
                        #pragma unroll
                        for (int dc = 0; dc < 8; dc++)
                            fma2(acc0[dc], xv[dc + 6 - q], wv[p*7 + q]);
                }
                if (l >= 1) {          // dr=1 row, p = 3-l
                    const int p = 3 - l;
                    #pragma unroll
                    for (int q = 0; q < 7; q++)
                        #pragma unroll
                        for (int dc = 0; dc < 8; dc++)
                            fma2(acc1[dc], xv[dc + 6 - q], wv[p*7 + q]);
                }
            }
        }
    }
    // maxpool 2x4 over acc0/acc1 -> pooled cols 2cp, 2cp+1
    float bb = b2[co];
    #pragma unroll
    for (int half = 0; half < 2; half++) {
        float2 a = up2(acc0[half*4]);
        float mx = a.x, my = a.y;
        #pragma unroll
        for (int dc = 1; dc < 4; dc++) {
            float2 u = up2(acc0[half*4 + dc]);
            mx = fmaxf(mx, u.x); my = fmaxf(my, u.y);
        }
        #pragma unroll
        for (int dc = 0; dc < 4; dc++) {
            float2 u = up2(acc1[half*4 + dc]);
            mx = fmaxf(mx, u.x); my = fmaxf(my, u.y);
        }
        int pc = 2*cp + half;
        g_a2[((b0 *50 + co)*16 + r)*16 + pc] = fmaxf(mx + bb, 0.f);
        g_a2[((b1i*50 + co)*16 + r)*16 + pc] = fmaxf(my + bb, 0.f);
    }
}

// ---------------------------------------------------------------------------
// K3: combine: out[b] = a2[2b] + mean_{hw}(a2[2b+1]).  grid 800 = 16*50.
// ---------------------------------------------------------------------------
__global__ void k3() {
    const int bc = blockIdx.x;
    const int b = bc / 50, c = bc % 50;
    const int t = threadIdx.x;
    const float* ev = g_a2 + ((2*b)*50 + c)*256;
    const float* od = g_a2 + ((2*b + 1)*50 + c)*256;
    __shared__ float red[256];
    red[t] = od[t];
    __syncthreads();
    for (int s = 128; s > 0; s >>= 1) {
        if (t < s) red[t] += red[t + s];
        __syncthreads();
    }
    float mean = red[0] * (1.f/256.f);
    g_a2c[(b*50 + c)*256 + t] = ev[t] + mean;
}

// ---------------------------------------------------------------------------
// K4: zero-upsample(2,4) + conv3 (50->50, 3x5 circular on 32x64) + relu.
// (R2 scalar version — broadcast loads, compute/latency adequate.)
// ---------------------------------------------------------------------------
__global__ void k4(const float* __restrict__ w3, const float* __restrict__ b3) {
    __shared__ float sxd[50][2][16];
    const int b = blockIdx.y, h = blockIdx.x;
    const int tid = threadIdx.x;
    const int hodd = h & 1;
    const int pA = hodd ? 1 : 0;
    const int rowA = ((h - pA) & 31) >> 1;
    const int rowB = ((h - 2) & 31) >> 1;
    for (int idx = tid; idx < 1600; idx += 256) {
        int cin = idx >> 5, slot = (idx >> 4) & 1, col = idx & 15;
        int row = slot ? rowB : rowA;
        sxd[cin][slot][col] = g_a2c[((b*50 + cin)*16 + row)*16 + col];
    }
    __syncthreads();

    if (tid < 200) {
        const int co = tid >> 2, cls = tid & 3;
        float acc[16];
        #pragma unroll
        for (int j = 0; j < 16; j++) acc[j] = 0.f;

        #pragma unroll 2
        for (int cin = 0; cin < 50; cin++) {
            const float* wp = w3 + (co*50 + cin)*15;
            {
                float xr[16];
                #pragma unroll
                for (int jj = 0; jj < 4; jj++) {
                    float4 v = *(const float4*)&sxd[cin][0][jj*4];
                    xr[jj*4+0] = v.x; xr[jj*4+1] = v.y;
                    xr[jj*4+2] = v.z; xr[jj*4+3] = v.w;
                }
                float w0 = __ldg(&wp[pA*5 + cls]);
                #pragma unroll
                for (int j = 0; j < 16; j++) acc[j] += w0 * xr[j];
                if (cls == 0) {
                    float w1 = __ldg(&wp[pA*5 + 4]);
                    #pragma unroll
                    for (int j = 0; j < 16; j++)
                        acc[j] += w1 * xr[(j + 15) & 15];
                }
            }
            if (!hodd) {
                float xr[16];
                #pragma unroll
                for (int jj = 0; jj < 4; jj++) {
                    float4 v = *(const float4*)&sxd[cin][1][jj*4];
                    xr[jj*4+0] = v.x; xr[jj*4+1] = v.y;
                    xr[jj*4+2] = v.z; xr[jj*4+3] = v.w;
                }
                float w0 = __ldg(&wp[10 + cls]);
                #pragma unroll
                for (int j = 0; j < 16; j++) acc[j] += w0 * xr[j];
                if (cls == 0) {
                    float w1 = __ldg(&wp[10 + 4]);
                    #pragma unroll
                    for (int j = 0; j < 16; j++)
                        acc[j] += w1 * xr[(j + 15) & 15];
                }
            }
        }
        float bb = b3[co];
        #pragma unroll
        for (int j = 0; j < 16; j++)
            g_a3[((b*50 + co)*32 + h)*64 + cls + 4*j] =
                fmaxf(acc[j] + bb, 0.f);
    }
}

// ---------------------------------------------------------------------------
// K5: zero-upsample(2,4) + conv4 (50->50, 3x7 circular on 64x256) + relu.
// f32x2 batch-paired, 16 output cols per thread (quarter tiles) so acc stays
// at 32 regs. All x-loads warp-broadcast; weights from L2 feed 16-32 fma2.
// grid (256 = 64 h x 4 qt, 8 bpairs), 224 threads; t<200: co=t/4, cls=t%4.
// ---------------------------------------------------------------------------
__global__ void __launch_bounds__(224, 3)
k5(const float* __restrict__ w4, const float* __restrict__ b4) {
    __shared__ float2 sxd[50][2][18];   // 17 downsampled cols (+pad)
    const int bp = blockIdx.y, bx = blockIdx.x;
    const int h = bx >> 2, qt = bx & 3;
    const int b0 = 2*bp, b1i = 2*bp + 1;
    const int tid = threadIdx.x;
    const int hodd = h & 1;
    const int pA = hodd ? 1 : 0;
    const int rowA = ((h - pA) & 63) >> 1;
    const int rowB = ((h - 2) & 63) >> 1;
    const float* a3b0 = g_a3 + b0*50*2048;
    const float* a3b1 = g_a3 + b1i*50*2048;
    for (int idx = tid; idx < 50*2*17; idx += 224) {
        int cin = idx / 34, s2 = idx % 34;
        int slot = s2 / 17, k = s2 % 17;
        int m = (qt*16 - 1 + k) & 63;
        int row = slot ? rowB : rowA;
        int off = (cin*32 + row)*64 + m;
        sxd[cin][slot][k] = make_float2(a3b0[off], a3b1[off]);
    }
    __syncthreads();

    if (tid < 200) {
        const int co = tid >> 2, cls = tid & 3;
        u64 acc[16];
        #pragma unroll
        for (int j = 0; j < 16; j++) acc[j] = 0ULL;

        for (int cin = 0; cin < 50; cin++) {
            const float* wp = w4 + (co*50 + cin)*21;
            {
                u64 xr[17];
                #pragma unroll
                for (int jj = 0; jj < 8; jj++) {
                    ulonglong2 v = *(const ulonglong2*)&sxd[cin][0][jj*2];
                    xr[jj*2] = v.x; xr[jj*2+1] = v.y;
                }
                xr[16] = lds2(&sxd[cin][0][16]);
                float w0s = __ldg(&wp[pA*7 + cls]);
                u64 w0 = pk2(w0s, w0s);
                #pragma unroll
                for (int j = 0; j < 16; j++) fma2(acc[j], xr[j+1], w0);
                if (cls < 3) {
                    float w1s = __ldg(&wp[pA*7 + cls + 4]);
                    u64 w1 = pk2(w1s, w1s);
                    #pragma unroll
                    for (int j = 0; j < 16; j++) fma2(acc[j], xr[j], w1);
                }
            }
            if (!hodd) {
                u64 xr[17];
                #pragma unroll
                for (int jj = 0; jj < 8; jj++) {
                    ulonglong2 v = *(const ulonglong2*)&sxd[cin][1][jj*2];
                    xr[jj*2] = v.x; xr[jj*2+1] = v.y;
                }
                xr[16] = lds2(&sxd[cin][1][16]);
                float w0s = __ldg(&wp[14 + cls]);
                u64 w0 = pk2(w0s, w0s);
                #pragma unroll
                for (int j = 0; j < 16; j++) fma2(acc[j], xr[j+1], w0);
                if (cls < 3) {
                    float w1s = __ldg(&wp[14 + cls + 4]);
                    u64 w1 = pk2(w1s, w1s);
                    #pragma unroll
                    for (int j = 0; j < 16; j++) fma2(acc[j], xr[j], w1);
                }
            }
        }
        float bb = b4[co];
        #pragma unroll
        for (int j = 0; j < 16; j++) {
            float2 a = up2(acc[j]);
            int off = (co*64 + h)*256 + cls + 4*(qt*16 + j);
            g_a4[b0 *50*16384 + off] = fmaxf(a.x + bb, 0.f);
            g_a4[b1i*50*16384 + off] = fmaxf(a.y + bb, 0.f);
        }
    }
}

// ---------------------------------------------------------------------------
// K6: conv5 (50->1, 3x7 circular on 64x256) + sigmoid. Scalar.
// grid (16 h-quads, 32 b), 128 threads: colg = tid&31 (8 cols), i = tid>>5
// (output row h0+i). Register x-rotation: 56 FFMA per 14-element row load;
// skewed smem kills the stride-8 bank conflicts.
// ---------------------------------------------------------------------------
__global__ void __launch_bounds__(128, 4)
k6(const float* __restrict__ w5, const float* __restrict__ b5,
   float* __restrict__ out) {
    __shared__ float sxc[5][6][288];    // [cin-chunk][input row][skewed col]
    __shared__ float sw[1050];
    const int bp = blockIdx.y, hq = blockIdx.x;
    const int h0 = hq*4;
    const int b = bp;
    const int tid = threadIdx.x;
    const int colg = tid & 31, i = tid >> 5;
    const float* a4b = g_a4 + b*50*16384;
    for (int idx = tid; idx < 1050; idx += 128) sw[idx] = w5[idx];

    float acc[8];
    #pragma unroll
    for (int c = 0; c < 8; c++) acc[c] = 0.f;

    #pragma unroll 1
    for (int cb = 0; cb < 50; cb += 5) {
        __syncthreads();
        for (int idx = tid; idx < 5*6*256; idx += 128) {
            int cl = idx / 1536, rr = (idx >> 8) % 6, m = idx & 255;
            int inrow = (h0 - 2 + rr) & 63;
            sxc[cl][rr][swz(m)] = a4b[((cb + cl)*64 + inrow)*256 + m];
        }
        __syncthreads();
        #pragma unroll 1
        for (int cl = 0; cl < 5; cl++) {
            float wv[21];
            #pragma unroll
            for (int t = 0; t < 21; t++) wv[t] = sw[(cb + cl)*21 + t];
            #pragma unroll
            for (int dp = 0; dp < 3; dp++) {
                int rr = i + dp;           // input row index
                int p = 2 - dp;            // tap row
                float xv[14];
                #pragma unroll
                for (int j = 0; j < 14; j++) {
                    int m = (colg*8 - 6 + j) & 255;
                    xv[j] = sxc[cl][rr][swz(m)];
                }
                #pragma unroll
                for (int q = 0; q < 7; q++) {
                    float w = wv[p*7 + q];
                    #pragma unroll
                    for (int c = 0; c < 8; c++)
                        acc[c] += w * xv[c + 6 - q];
                }
            }
        }
    }
    float bb = b5[0];
    #pragma unroll
    for (int c = 0; c < 8; c++) {
        float z = acc[c] + bb;
        out[(b*64 + h0 + i)*256 + colg*8 + c] = 1.f / (1.f + expf(-z));
    }
}

// ---------------------------------------------------------------------------
extern "C" void kernel_launch(void* const* d_in, const int* in_sizes, int n_in,
                              void* d_out, int out_size) {
    const float* x  = (const float*)d_in[0];
    const float* w1 = (const float*)d_in[1];
    const float* b1 = (const float*)d_in[2];
    const float* w2 = (const float*)d_in[3];
    const float* b2 = (const float*)d_in[4];
    const float* w3 = (const float*)d_in[5];
    const float* b3 = (const float*)d_in[6];
    const float* w4 = (const float*)d_in[7];
    const float* b4 = (const float*)d_in[8];
    const float* w5 = (const float*)d_in[9];
    const float* b5 = (const float*)d_in[10];
    float* out = (float*)d_out;

    k1<<<dim3(8, 32), 256>>>(x, w1, b1);
    k2<<<dim3(32, 16), 200>>>(w2, b2);
    k3<<<800, 256>>>();
    k4<<<dim3(32, 16), 256>>>(w3, b3);
    k5<<<dim3(256, 8), 224>>>(w4, b4);
    k6<<<dim3(16, 16), 128>>>(w5, b5, out);
}